// round 3
// baseline (speedup 1.0000x reference)
#include <cuda_runtime.h>
#include <cooperative_groups.h>
namespace cg = cooperative_groups;

#define TSTEPS 512
#define BATCH  256
#define ISZ    64
#define HSZ    256
#define KEXT   (HSZ + ISZ)      // 320
#define BCTA   4                // batch rows per cluster
#define JHALF  128              // output cols per CTA
#define NTH    256
#define KC     8                // K-chunks = warps
#define KROWS  (KEXT / KC)      // 40
#define NBLOCKS ((BATCH / BCTA) * 2)  // 128 CTAs

__device__ float g_WT[KEXT * HSZ];  // W_ext^T [i][j]
__device__ float g_bias[HSZ];

__global__ void prep_kernel(const float* __restrict__ W_ih,
                            const float* __restrict__ W_hh,
                            const float* __restrict__ b_ih,
                            const float* __restrict__ b_hh) {
    int idx = blockIdx.x * blockDim.x + threadIdx.x;
    int stride = gridDim.x * blockDim.x;
    for (int p = idx; p < KEXT * HSZ; p += stride) {
        int i = p >> 8, j = p & 255;
        g_WT[p] = (i < HSZ) ? W_hh[j * HSZ + i] : W_ih[j * ISZ + (i - HSZ)];
    }
    if (idx < HSZ) g_bias[idx] = b_ih[idx] + b_hh[idx];
}

#define SDUP  (KEXT * BCTA * 2)       // 2560 floats per state buffer (duplicated)
#define RED_F (KC * BCTA * JHALF)     // 4096

// packed f32x2 fma: d = a*b + d (elementwise on 2 packed floats)
#define FMA2(d, a, b) asm volatile("fma.rn.f32x2 %0, %1, %2, %0;" : "+l"(d) : "l"(a), "l"(b))

static __device__ __forceinline__ unsigned s2u(const void* p) {
    return (unsigned)__cvta_generic_to_shared(p);
}
static __device__ __forceinline__ unsigned long long dup2(float v) {
    unsigned long long d;
    asm("mov.b64 %0, {%1, %1};" : "=l"(d) : "f"(v));
    return d;
}
static __device__ __forceinline__ void bar_arrive_local(unsigned bar) {
    asm volatile("mbarrier.arrive.release.cta.shared::cta.b64 _, [%0];" :: "r"(bar) : "memory");
}
static __device__ __forceinline__ void bar_arrive_remote(unsigned bar, unsigned peer) {
    asm volatile("{\n\t.reg .b32 ra;\n\t"
                 "mapa.shared::cluster.u32 ra, %0, %1;\n\t"
                 "mbarrier.arrive.release.cluster.shared::cluster.b64 _, [ra];\n\t}"
                 :: "r"(bar), "r"(peer) : "memory");
}
static __device__ __forceinline__ void bar_wait(unsigned bar, unsigned phase) {
    asm volatile("{\n\t.reg .pred P;\n\t"
                 "WLOOP_%=:\n\t"
                 "mbarrier.try_wait.parity.acquire.cluster.shared::cta.b64 P, [%0], %1, 0x989680;\n\t"
                 "@P bra.uni WDONE_%=;\n\t"
                 "bra.uni WLOOP_%=;\n\t"
                 "WDONE_%=:\n\t}"
                 :: "r"(bar), "r"(phase) : "memory");
}

__global__ void __cluster_dims__(2, 1, 1) __launch_bounds__(NTH, 1)
rnn_kernel(const float* __restrict__ x,
           const float* __restrict__ fc_W,
           const float* __restrict__ fc_b,
           float* __restrict__ out) {
    __shared__ float S[2 * SDUP];                 // duplicated state, double buffered
    __shared__ float red[RED_F];
    __shared__ float biasS[JHALF];
    __shared__ __align__(8) unsigned long long barrier_s;

    cg::cluster_group cl = cg::this_cluster();
    const int rank = (int)cl.block_rank();
    const int tid  = threadIdx.x;
    const int lane = tid & 31;
    const int kc   = tid >> 5;
    const int b0   = (blockIdx.x >> 1) * BCTA;
    const unsigned barA = s2u(&barrier_s);

    // ---- weights into registers: 40 rows x 4 cols -> 40 ulonglong2 (two f32x2 pairs each)
    ulonglong2 wreg[KROWS];
    {
        const ulonglong2* GW = reinterpret_cast<const ulonglong2*>(g_WT);
        int cb4 = ((rank << 7) + (lane << 2)) >> 2;   // col base / 4
        #pragma unroll
        for (int ii = 0; ii < KROWS; ++ii)
            wreg[ii] = GW[(kc * KROWS + ii) * 64 + cb4];
    }
    if (tid < JHALF) biasS[tid] = g_bias[(rank << 7) + tid];

    // ---- init state buffer 0: h=0 (dup), x0 (dup)
    for (int p = tid; p < HSZ * BCTA * 2; p += NTH) S[p] = 0.f;
    for (int p = tid; p < ISZ * BCTA; p += NTH) {
        int b = p >> 6, i = p & 63;
        float v = x[(b0 + b) * TSTEPS * ISZ + i];
        S[(HSZ + i) * 8 + 2 * b]     = v;
        S[(HSZ + i) * 8 + 2 * b + 1] = v;
    }
    if (tid == 0) {
        asm volatile("mbarrier.init.shared.b64 [%0], 12;" :: "r"(barA) : "memory");
    }
    __syncthreads();
    asm volatile("barrier.cluster.arrive.aligned;" ::: "memory");
    asm volatile("barrier.cluster.wait.aligned;" ::: "memory");

    float* peerS = (float*)cl.map_shared_rank((void*)S, rank ^ 1);
    const float* xb = x + (size_t)b0 * TSTEPS * ISZ;
    const int peer = rank ^ 1;

    int cur = 0;
    unsigned phase = 0;
    for (int t = 0; t < TSTEPS; ++t) {
        float* scur  = S + cur * SDUP;
        float* snxt  = S + (cur ^ 1) * SDUP;
        float* psnxt = peerS + (cur ^ 1) * SDUP;

        // hoisted x prefetch (warps 4-7): latency hides under the GEMM
        float xv0 = 0.f, xv1 = 0.f;
        if (kc >= 4 && t + 1 < TSTEPS) {
            int p = tid - JHALF;
            xv0 = xb[(size_t)((p >> 6)) * TSTEPS * ISZ + (size_t)(t + 1) * ISZ + (p & 63)];
            int q = p + JHALF;
            xv1 = xb[(size_t)((q >> 6)) * TSTEPS * ISZ + (size_t)(t + 1) * ISZ + (q & 63)];
        }

        // ---- GEMM: weights resident in regs, state via broadcast LDS
        unsigned long long a0 = 0, a1 = 0, a2 = 0, a3 = 0, a4 = 0, a5 = 0, a6 = 0, a7 = 0;
        const ulonglong2* S2 = reinterpret_cast<const ulonglong2*>(scur) + kc * KROWS * 2;
        #pragma unroll
        for (int ii = 0; ii < KROWS; ++ii) {
            ulonglong2 hA = S2[ii * 2];       // {h0h0, h1h1}
            ulonglong2 hB = S2[ii * 2 + 1];   // {h2h2, h3h3}
            FMA2(a0, wreg[ii].x, hA.x);  FMA2(a1, wreg[ii].y, hA.x);   // b0
            FMA2(a2, wreg[ii].x, hA.y);  FMA2(a3, wreg[ii].y, hA.y);   // b1
            FMA2(a4, wreg[ii].x, hB.x);  FMA2(a5, wreg[ii].y, hB.x);   // b2
            FMA2(a6, wreg[ii].x, hB.y);  FMA2(a7, wreg[ii].y, hB.y);   // b3
        }

        // ---- partials: red[(kc*4+b)][cols 4*lane..+3], stored as ulonglong2 (no unpack)
        {
            ulonglong2* R2 = reinterpret_cast<ulonglong2*>(red);
            ulonglong2 v;
            v.x = a0; v.y = a1; R2[(kc * 4 + 0) * 32 + lane] = v;
            v.x = a2; v.y = a3; R2[(kc * 4 + 1) * 32 + lane] = v;
            v.x = a4; v.y = a5; R2[(kc * 4 + 2) * 32 + lane] = v;
            v.x = a6; v.y = a7; R2[(kc * 4 + 3) * 32 + lane] = v;
        }
        __syncthreads();

        if (tid < JHALF) {   // warps 0-3: reduce + tanh + publish dup state (local + DSMEM)
            float v0 = biasS[tid], v1 = v0, v2 = v0, v3 = v0;
            #pragma unroll
            for (int k = 0; k < KC; ++k) {
                v0 += red[(k * 4 + 0) * JHALF + tid];
                v1 += red[(k * 4 + 1) * JHALF + tid];
                v2 += red[(k * 4 + 2) * JHALF + tid];
                v3 += red[(k * 4 + 3) * JHALF + tid];
            }
            ulonglong2 d01, d23;
            d01.x = dup2(tanhf(v0)); d01.y = dup2(tanhf(v1));
            d23.x = dup2(tanhf(v2)); d23.y = dup2(tanhf(v3));
            int jg = (rank << 7) + tid;
            ulonglong2* L = reinterpret_cast<ulonglong2*>(snxt);
            ulonglong2* P = reinterpret_cast<ulonglong2*>(psnxt);
            L[jg * 2] = d01; L[jg * 2 + 1] = d23;
            P[jg * 2] = d01; P[jg * 2 + 1] = d23;
        } else if (t + 1 < TSTEPS) {   // warps 4-7: store prefetched x (dup)
            int p = tid - JHALF;
            int b = p >> 6, i = p & 63;
            snxt[(HSZ + i) * 8 + 2 * b]     = xv0;
            snxt[(HSZ + i) * 8 + 2 * b + 1] = xv0;
            int q = p + JHALF;
            int b2 = q >> 6, i2 = q & 63;
            snxt[(HSZ + i2) * 8 + 2 * b2]     = xv1;
            snxt[(HSZ + i2) * 8 + 2 * b2 + 1] = xv1;
        }

        // ---- arrivals: every warp -> local bar; reduce warps also -> peer bar (12 total)
        if (lane == 0) {
            bar_arrive_local(barA);
            if (kc < 4) bar_arrive_remote(barA, peer);
        }
        bar_wait(barA, phase);
        phase ^= 1;
        cur ^= 1;
    }

    // ---- final FC (O=1): out[b] = sum_j h_T[j][b] * fc_W[j] + fc_b
    if (rank == 0) {
        float* scur = S + cur * SDUP;
        float fw = fc_W[tid];
        float p0 = scur[tid * 8 + 0] * fw;
        float p1 = scur[tid * 8 + 2] * fw;
        float p2 = scur[tid * 8 + 4] * fw;
        float p3 = scur[tid * 8 + 6] * fw;
        #pragma unroll
        for (int off = 16; off; off >>= 1) {
            p0 += __shfl_down_sync(0xffffffffu, p0, off);
            p1 += __shfl_down_sync(0xffffffffu, p1, off);
            p2 += __shfl_down_sync(0xffffffffu, p2, off);
            p3 += __shfl_down_sync(0xffffffffu, p3, off);
        }
        __syncthreads();
        if (lane == 0) {
            red[kc * 4 + 0] = p0; red[kc * 4 + 1] = p1;
            red[kc * 4 + 2] = p2; red[kc * 4 + 3] = p3;
        }
        __syncthreads();
        if (tid < 4) {
            float v = fc_b[0];
            #pragma unroll
            for (int k = 0; k < KC; ++k) v += red[k * 4 + tid];
            out[b0 + tid] = v;
        }
    }
}

extern "C" void kernel_launch(void* const* d_in, const int* in_sizes, int n_in,
                              void* d_out, int out_size) {
    const float* x    = (const float*)d_in[0];
    const float* W_ih = (const float*)d_in[1];
    const float* W_hh = (const float*)d_in[2];
    const float* b_ih = (const float*)d_in[3];
    const float* b_hh = (const float*)d_in[4];
    const float* fc_W = (const float*)d_in[5];
    const float* fc_b = (const float*)d_in[6];
    float* out = (float*)d_out;

    prep_kernel<<<128, 256>>>(W_ih, W_hh, b_ih, b_hh);
    rnn_kernel<<<NBLOCKS, NTH>>>(x, fc_W, fc_b, out);
}

// round 5
// speedup vs baseline: 1.2129x; 1.2129x over previous
#include <cuda_runtime.h>
#include <cooperative_groups.h>
namespace cg = cooperative_groups;

#define TSTEPS 512
#define BATCH  256
#define ISZ    64
#define HSZ    256
#define KEXT   (HSZ + ISZ)        // 320
#define BCTA   4                  // batch rows per cluster
#define JHALF  128                // output cols per CTA
#define NTH    512
#define KC     16                 // K-chunks = warps
#define KROWS  (KEXT / KC)        // 20
#define NBLOCKS ((BATCH / BCTA) * 2)   // 128 CTAs

__device__ float g_WT[KEXT * HSZ];   // W_ext^T [i][j]
__device__ float g_bias[HSZ];

__global__ void prep_kernel(const float* __restrict__ W_ih,
                            const float* __restrict__ W_hh,
                            const float* __restrict__ b_ih,
                            const float* __restrict__ b_hh) {
    int idx = blockIdx.x * blockDim.x + threadIdx.x;
    int stride = gridDim.x * blockDim.x;
    for (int p = idx; p < KEXT * HSZ; p += stride) {
        int i = p >> 8, j = p & 255;
        g_WT[p] = (i < HSZ) ? W_hh[j * HSZ + i] : W_ih[j * ISZ + (i - HSZ)];
    }
    if (idx < HSZ) g_bias[idx] = b_ih[idx] + b_hh[idx];
}

#define SDUP   (KEXT * BCTA * 2)      // 2560 floats per state buffer (dup'd)
// padded partial-sum scratch: f32 idx = k*544 + b*136 + j  (j in [0,128))
#define REDK   272                    // u64 stride per k-block (= 544 floats)
#define REDB   68                     // u64 stride per batch  (= 136 floats)
#define RED_U64 (KC * REDK)           // 4352 u64 = 34816 B
#define SMEM_BYTES (2 * SDUP * 4 + RED_U64 * 8)   // 20480 + 34816 = 55296

#define FMA2(d, a, b) asm volatile("fma.rn.f32x2 %0, %1, %2, %0;" : "+l"(d) : "l"(a), "l"(b))

static __device__ __forceinline__ unsigned s2u(const void* p) {
    return (unsigned)__cvta_generic_to_shared(p);
}
static __device__ __forceinline__ unsigned long long dup2(float v) {
    unsigned long long d;
    asm("mov.b64 %0, {%1, %1};" : "=l"(d) : "f"(v));
    return d;
}
static __device__ __forceinline__ void bar_arrive_local(unsigned bar) {
    asm volatile("mbarrier.arrive.release.cta.shared::cta.b64 _, [%0];" :: "r"(bar) : "memory");
}
static __device__ __forceinline__ void bar_arrive_remote(unsigned bar, unsigned peer) {
    asm volatile("{\n\t.reg .b32 ra;\n\t"
                 "mapa.shared::cluster.u32 ra, %0, %1;\n\t"
                 "mbarrier.arrive.release.cluster.shared::cluster.b64 _, [ra];\n\t}"
                 :: "r"(bar), "r"(peer) : "memory");
}
static __device__ __forceinline__ void bar_wait(unsigned bar, unsigned phase) {
    asm volatile("{\n\t.reg .pred P;\n\t"
                 "WLOOP_%=:\n\t"
                 "mbarrier.try_wait.parity.acquire.cluster.shared::cta.b64 P, [%0], %1, 0x989680;\n\t"
                 "@P bra.uni WDONE_%=;\n\t"
                 "bra.uni WLOOP_%=;\n\t"
                 "WDONE_%=:\n\t}"
                 :: "r"(bar), "r"(phase) : "memory");
}

__global__ void __cluster_dims__(2, 1, 1) __launch_bounds__(NTH, 1)
rnn_kernel(const float* __restrict__ x,
           const float* __restrict__ fc_W,
           const float* __restrict__ fc_b,
           float* __restrict__ out) {
    extern __shared__ float smdyn[];
    float* S = smdyn;                                            // 2*SDUP floats
    unsigned long long* red2 =
        reinterpret_cast<unsigned long long*>(smdyn + 2 * SDUP); // RED_U64 u64
    __shared__ __align__(8) unsigned long long barrier_s;

    cg::cluster_group cl = cg::this_cluster();
    const int rank = (int)cl.block_rank();
    const int tid  = threadIdx.x;
    const int lane = tid & 31;
    const int kc   = tid >> 5;                 // warp = K-chunk (0..15)
    const int b0   = (blockIdx.x >> 1) * BCTA;
    const unsigned barA = s2u(&barrier_s);
    const int peer = rank ^ 1;

    // ---- weights into registers: 20 rows x 2 col-pairs (u64 each)
    unsigned long long w0[KROWS], w1[KROWS];
    {
        const int cb = rank * JHALF + 2 * lane;
        #pragma unroll
        for (int ii = 0; ii < KROWS; ++ii) {
            int i = kc * KROWS + ii;
            w0[ii] = *reinterpret_cast<const unsigned long long*>(&g_WT[i * HSZ + cb]);
            w1[ii] = *reinterpret_cast<const unsigned long long*>(&g_WT[i * HSZ + cb + 64]);
        }
    }
    const float breg = g_bias[rank * JHALF + (tid >> 2)];

    // ---- init state buffer 0: h = 0 (dup), x0 (dup)
    for (int p = tid; p < HSZ * BCTA * 2; p += NTH) S[p] = 0.f;
    if (tid < ISZ * BCTA) {
        int b = tid >> 6, i = tid & 63;
        float v = x[(b0 + b) * TSTEPS * ISZ + i];
        reinterpret_cast<unsigned long long*>(S)[(HSZ + i) * 4 + b] = dup2(v);
    }
    if (tid == 0)
        asm volatile("mbarrier.init.shared.b64 [%0], 2;" :: "r"(barA) : "memory");
    __syncthreads();
    asm volatile("barrier.cluster.arrive.aligned;" ::: "memory");
    asm volatile("barrier.cluster.wait.aligned;" ::: "memory");

    float* peerS = (float*)cl.map_shared_rank((void*)S, peer);
    const float* xb = x + (size_t)b0 * TSTEPS * ISZ;

    int cur = 0;
    unsigned phase = 0;
    for (int t = 0; t < TSTEPS; ++t) {
        float* scur  = S + cur * SDUP;
        float* snxt  = S + (cur ^ 1) * SDUP;
        float* psnxt = peerS + (cur ^ 1) * SDUP;

        // hoisted x_{t+1} prefetch (threads 0..255): LDG hides under GEMM
        float xv = 0.f;
        if (tid < ISZ * BCTA && t + 1 < TSTEPS)
            xv = xb[(size_t)(tid >> 6) * TSTEPS * ISZ + (size_t)(t + 1) * ISZ + (tid & 63)];

        // ---- GEMM: weights in regs, dup state via broadcast LDS.128
        unsigned long long a0 = 0, a1 = 0, a2 = 0, a3 = 0, a4 = 0, a5 = 0, a6 = 0, a7 = 0;
        const ulonglong2* S2 = reinterpret_cast<const ulonglong2*>(scur) + kc * KROWS * 2;
        #pragma unroll
        for (int ii = 0; ii < KROWS; ++ii) {
            ulonglong2 hA = S2[ii * 2];       // {b0b0, b1b1}
            ulonglong2 hB = S2[ii * 2 + 1];   // {b2b2, b3b3}
            FMA2(a0, w0[ii], hA.x);  FMA2(a1, w1[ii], hA.x);   // b0
            FMA2(a2, w0[ii], hA.y);  FMA2(a3, w1[ii], hA.y);   // b1
            FMA2(a4, w0[ii], hB.x);  FMA2(a5, w1[ii], hB.x);   // b2
            FMA2(a6, w0[ii], hB.y);  FMA2(a7, w1[ii], hB.y);   // b3
        }

        // ---- partials: red2[kc*272 + b*68 + p], p = lane (pair0) / 32+lane (pair1)
        {
            unsigned long long* R = red2 + kc * REDK + lane;
            R[0 * REDB]      = a0;  R[0 * REDB + 32] = a1;
            R[1 * REDB]      = a2;  R[1 * REDB + 32] = a3;
            R[2 * REDB]      = a4;  R[2 * REDB + 32] = a5;
            R[3 * REDB]      = a6;  R[3 * REDB + 32] = a7;
        }
        __syncthreads();

        // ---- reduce + tanh + publish: thread -> (j = tid>>2, b = tid&3)
        {
            const int j = tid >> 2, b = tid & 3;
            const float* rf = reinterpret_cast<const float*>(red2) + b * (2 * REDB) + j;
            float v = breg;
            #pragma unroll
            for (int k = 0; k < KC; ++k) v += rf[k * (2 * REDK)];
            unsigned long long hd = dup2(tanhf(v));
            int idx = (rank * JHALF + j) * 4 + b;
            reinterpret_cast<unsigned long long*>(snxt)[idx]  = hd;
            reinterpret_cast<unsigned long long*>(psnxt)[idx] = hd;   // DSMEM
        }
        if (tid < ISZ * BCTA && t + 1 < TSTEPS) {   // store prefetched x (dup)
            int b = tid >> 6, i = tid & 63;
            reinterpret_cast<unsigned long long*>(snxt)[(HSZ + i) * 4 + b] = dup2(xv);
        }
        __syncthreads();
        if (tid == 0) { bar_arrive_local(barA); bar_arrive_remote(barA, peer); }
        bar_wait(barA, phase);
        phase ^= 1;
        cur ^= 1;
    }

    // ---- final FC (O=1): out[b] = sum_j h_T[j][b]*fc_W[j] + fc_b   (rank 0 only)
    if (rank == 0) {
        float* scur = S + cur * SDUP;
        float* redf = reinterpret_cast<float*>(red2);
        if (tid < HSZ) {
            float fw = fc_W[tid];
            float p0 = scur[tid * 8 + 0] * fw;
            float p1 = scur[tid * 8 + 2] * fw;
            float p2 = scur[tid * 8 + 4] * fw;
            float p3 = scur[tid * 8 + 6] * fw;
            #pragma unroll
            for (int off = 16; off; off >>= 1) {
                p0 += __shfl_down_sync(0xffffffffu, p0, off);
                p1 += __shfl_down_sync(0xffffffffu, p1, off);
                p2 += __shfl_down_sync(0xffffffffu, p2, off);
                p3 += __shfl_down_sync(0xffffffffu, p3, off);
            }
            if (lane == 0) {
                redf[kc * 4 + 0] = p0; redf[kc * 4 + 1] = p1;
                redf[kc * 4 + 2] = p2; redf[kc * 4 + 3] = p3;
            }
        }
        __syncthreads();
        if (tid < 4) {
            float v = fc_b[0];
            #pragma unroll
            for (int k = 0; k < 8; ++k) v += redf[k * 4 + tid];
            out[b0 + tid] = v;
        }
    }
}

extern "C" void kernel_launch(void* const* d_in, const int* in_sizes, int n_in,
                              void* d_out, int out_size) {
    const float* x    = (const float*)d_in[0];
    const float* W_ih = (const float*)d_in[1];
    const float* W_hh = (const float*)d_in[2];
    const float* b_ih = (const float*)d_in[3];
    const float* b_hh = (const float*)d_in[4];
    const float* fc_W = (const float*)d_in[5];
    const float* fc_b = (const float*)d_in[6];
    float* out = (float*)d_out;

    cudaFuncSetAttribute(rnn_kernel, cudaFuncAttributeMaxDynamicSharedMemorySize, SMEM_BYTES);

    prep_kernel<<<128, 256>>>(W_ih, W_hh, b_ih, b_hh);
    rnn_kernel<<<NBLOCKS, NTH, SMEM_BYTES>>>(x, fc_W, fc_b, out);
}

// round 6
// speedup vs baseline: 1.3318x; 1.0980x over previous
#include <cuda_runtime.h>
#include <cooperative_groups.h>
namespace cg = cooperative_groups;

#define TSTEPS 512
#define BATCH  256
#define ISZ    64
#define HSZ    256
#define KEXT   (HSZ + ISZ)        // 320
#define BCTA   4
#define JHALF  128
#define NTH    512
#define KC     16                 // warps
#define KH_W   (HSZ / KC)         // 16 h-rows per warp
#define KX_W   (ISZ / KC)         // 4 x-rows per warp
#define NBLOCKS ((BATCH / BCTA) * 2)   // 128

__device__ float g_WT[KEXT * HSZ];   // W_ext^T [i][j]: rows 0..255 = W_hh^T, 256..319 = W_ih^T
__device__ float g_bias[HSZ];

__global__ void prep_kernel(const float* __restrict__ W_ih,
                            const float* __restrict__ W_hh,
                            const float* __restrict__ b_ih,
                            const float* __restrict__ b_hh) {
    int idx = blockIdx.x * blockDim.x + threadIdx.x;
    int stride = gridDim.x * blockDim.x;
    for (int p = idx; p < KEXT * HSZ; p += stride) {
        int i = p >> 8, j = p & 255;
        g_WT[p] = (i < HSZ) ? W_hh[j * HSZ + i] : W_ih[j * ISZ + (i - HSZ)];
    }
    if (idx < HSZ) g_bias[idx] = b_ih[idx] + b_hh[idx];
}

// SMEM byte offsets
#define S_OFF    0          // h state, dup'd: 2 bufs x 256 rows x 4 u64  = 16384 B
#define X_OFF    16384      // x stage, dup'd: 2 bufs x 64 rows x 4 u64   =  4096 B
#define RED_OFF  20480      // partials: padded, 16*272 u64               = 34816 B
#define SMEM_BYTES 55296
#define SBUF_B   8192       // bytes per h-state buffer
#define XBUF_B   2048       // bytes per x-stage buffer
#define REDK     272        // u64 stride per k-chunk (=544 floats)
#define REDB     68         // u64 stride per batch   (=136 floats)

#define FMA2(d, a, b) asm volatile("fma.rn.f32x2 %0, %1, %2, %0;" : "+l"(d) : "l"(a), "l"(b))

static __device__ __forceinline__ unsigned s2u(const void* p) {
    return (unsigned)__cvta_generic_to_shared(p);
}
static __device__ __forceinline__ unsigned long long dup2(float v) {
    unsigned long long d;
    asm("mov.b64 %0, {%1, %1};" : "=l"(d) : "f"(v));
    return d;
}
static __device__ __forceinline__ float tanh_fast(float v) {
    // tanh(v) = 1 - 2/(exp(2v)+1); MUFU ex2 + rcp, ~1e-6 rel err, exact saturation
    float e, r;
    asm("ex2.approx.f32 %0, %1;" : "=f"(e) : "f"(v * 2.885390082f));
    asm("rcp.approx.f32 %0, %1;" : "=f"(r) : "f"(e + 1.0f));
    return 1.0f - 2.0f * r;
}
static __device__ __forceinline__ void lds_v2u64(unsigned long long& a, unsigned long long& b, unsigned ad) {
    asm volatile("ld.shared.v2.u64 {%0,%1}, [%2];" : "=l"(a), "=l"(b) : "r"(ad));
}
static __device__ __forceinline__ void sts_u64(unsigned ad, unsigned long long v) {
    asm volatile("st.shared.u64 [%0], %1;" :: "r"(ad), "l"(v) : "memory");
}
static __device__ __forceinline__ void sts_cluster_u64(unsigned ad, unsigned long long v) {
    asm volatile("st.shared::cluster.u64 [%0], %1;" :: "r"(ad), "l"(v) : "memory");
}
static __device__ __forceinline__ float lds_f32(unsigned ad) {
    float v;
    asm volatile("ld.shared.f32 %0, [%1];" : "=f"(v) : "r"(ad));
    return v;
}
static __device__ __forceinline__ void bar_arrive_local(unsigned bar) {
    asm volatile("mbarrier.arrive.release.cta.shared::cta.b64 _, [%0];" :: "r"(bar) : "memory");
}
static __device__ __forceinline__ void bar_arrive_remote_pre(unsigned bar_remote) {
    asm volatile("mbarrier.arrive.release.cluster.shared::cluster.b64 _, [%0];" :: "r"(bar_remote) : "memory");
}
static __device__ __forceinline__ void bar_wait(unsigned bar, unsigned phase) {
    asm volatile("{\n\t.reg .pred P;\n\t"
                 "WLOOP_%=:\n\t"
                 "mbarrier.try_wait.parity.acquire.cluster.shared::cta.b64 P, [%0], %1, 0x989680;\n\t"
                 "@P bra.uni WDONE_%=;\n\t"
                 "bra.uni WLOOP_%=;\n\t"
                 "WDONE_%=:\n\t}"
                 :: "r"(bar), "r"(phase) : "memory");
}
static __device__ __forceinline__ unsigned mapa_u32(unsigned ad, int peer) {
    unsigned r;
    asm("mapa.shared::cluster.u32 %0, %1, %2;" : "=r"(r) : "r"(ad), "r"(peer));
    return r;
}

__global__ void __cluster_dims__(2, 1, 1) __launch_bounds__(NTH, 1)
rnn_kernel(const float* __restrict__ x,
           const float* __restrict__ fc_W,
           const float* __restrict__ fc_b,
           float* __restrict__ out) {
    extern __shared__ float smdyn[];
    __shared__ __align__(8) unsigned long long barrier_s;

    cg::cluster_group cl = cg::this_cluster();
    const int rank = (int)cl.block_rank();
    const int tid  = threadIdx.x;
    const int lane = tid & 31;
    const int kc   = tid >> 5;
    const int b0   = (blockIdx.x >> 1) * BCTA;
    const int peer = rank ^ 1;

    const unsigned smbase = s2u(smdyn);
    const unsigned Sb   = smbase + S_OFF;
    const unsigned Xb   = smbase + X_OFF;
    const unsigned REDb = smbase + RED_OFF;
    const unsigned barA = s2u(&barrier_s);

    // ---- weights -> registers: h-part 16 rows, x-part 4 rows; 2 col-pairs each
    unsigned long long wh0[KH_W], wh1[KH_W], wx0[KX_W], wx1[KX_W];
    {
        const int cb = rank * JHALF + 2 * lane;
        #pragma unroll
        for (int ii = 0; ii < KH_W; ++ii) {
            int i = kc * KH_W + ii;
            wh0[ii] = *reinterpret_cast<const unsigned long long*>(&g_WT[i * HSZ + cb]);
            wh1[ii] = *reinterpret_cast<const unsigned long long*>(&g_WT[i * HSZ + cb + 64]);
        }
        #pragma unroll
        for (int ii = 0; ii < KX_W; ++ii) {
            int i = HSZ + kc * KX_W + ii;
            wx0[ii] = *reinterpret_cast<const unsigned long long*>(&g_WT[i * HSZ + cb]);
            wx1[ii] = *reinterpret_cast<const unsigned long long*>(&g_WT[i * HSZ + cb + 64]);
        }
    }
    const float breg = g_bias[rank * JHALF + (tid >> 2)];

    // ---- init: h buf0 = 0; stage x(0)->Xs[0], x(1)->Xs[1]
    for (int p = tid; p < 2 * HSZ * BCTA * 2; p += NTH) smdyn[p] = 0.f;   // both h bufs
    const float* xb = x + (size_t)b0 * TSTEPS * ISZ;
    if (tid < ISZ * BCTA) {
        int b = tid >> 6, i = tid & 63;
        sts_u64(Xb + (unsigned)(i * 4 + b) * 8,          dup2(xb[(size_t)b * TSTEPS * ISZ + i]));
        sts_u64(Xb + XBUF_B + (unsigned)(i * 4 + b) * 8, dup2(xb[(size_t)b * TSTEPS * ISZ + ISZ + i]));
    }
    if (tid == 0)
        asm volatile("mbarrier.init.shared.b64 [%0], 2;" :: "r"(barA) : "memory");
    __syncthreads();
    asm volatile("barrier.cluster.arrive.aligned;" ::: "memory");
    asm volatile("barrier.cluster.wait.aligned;" ::: "memory");

    const unsigned peerSb  = mapa_u32(Sb, peer);
    const unsigned peerBar = mapa_u32(barA, peer);

    // ---- acc = x-part(0) from Xs[0]
    unsigned long long a0 = 0, a1 = 0, a2 = 0, a3 = 0, a4 = 0, a5 = 0, a6 = 0, a7 = 0;
    {
        unsigned xadr = Xb + (unsigned)(kc * KX_W) * 32;
        #pragma unroll
        for (int ii = 0; ii < KX_W; ++ii) {
            unsigned long long hx, hy, hz, hw;
            lds_v2u64(hx, hy, xadr + ii * 32);
            lds_v2u64(hz, hw, xadr + ii * 32 + 16);
            FMA2(a0, wx0[ii], hx);  FMA2(a1, wx1[ii], hx);
            FMA2(a2, wx0[ii], hy);  FMA2(a3, wx1[ii], hy);
            FMA2(a4, wx0[ii], hz);  FMA2(a5, wx1[ii], hz);
            FMA2(a6, wx0[ii], hw);  FMA2(a7, wx1[ii], hw);
        }
    }

    int cur = 0;
    unsigned phase = 0;
    const int rj = tid >> 2, rb = tid & 3;                 // reduce mapping
    const unsigned pubIdx = (unsigned)((rank * JHALF + rj) * 4 + rb) * 8;
    const unsigned redLd  = REDb + (unsigned)(rb * 136 + rj) * 4;
    const unsigned redSt  = REDb + (unsigned)(kc * REDK + lane) * 8;
    const unsigned gAdr   = Sb + (unsigned)(kc * KH_W) * 32;   // + cur*SBUF_B

    for (int t = 0; t < TSTEPS; ++t) {
        // prefetch x(t+2)
        float xv = 0.f;
        if (tid < ISZ * BCTA && t + 2 < TSTEPS)
            xv = xb[(size_t)(tid >> 6) * TSTEPS * ISZ + (size_t)(t + 2) * ISZ + (tid & 63)];

        // ---- h-GEMM: 16 rows, acc already holds x-part(t)
        {
            unsigned sadr = gAdr + cur * SBUF_B;
            #pragma unroll
            for (int ii = 0; ii < KH_W; ++ii) {
                unsigned long long hx, hy, hz, hw;
                lds_v2u64(hx, hy, sadr + ii * 32);
                lds_v2u64(hz, hw, sadr + ii * 32 + 16);
                FMA2(a0, wh0[ii], hx);  FMA2(a1, wh1[ii], hx);
                FMA2(a2, wh0[ii], hy);  FMA2(a3, wh1[ii], hy);
                FMA2(a4, wh0[ii], hz);  FMA2(a5, wh1[ii], hz);
                FMA2(a6, wh0[ii], hw);  FMA2(a7, wh1[ii], hw);
            }
        }

        // ---- partials
        sts_u64(redSt,                 a0);  sts_u64(redSt + 32 * 8,            a1);
        sts_u64(redSt + REDB * 8,      a2);  sts_u64(redSt + (REDB + 32) * 8,   a3);
        sts_u64(redSt + 2 * REDB * 8,  a4);  sts_u64(redSt + (2 * REDB + 32) * 8, a5);
        sts_u64(redSt + 3 * REDB * 8,  a6);  sts_u64(redSt + (3 * REDB + 32) * 8, a7);
        __syncthreads();

        // ---- reduce (paired for ILP) + tanh + publish local & DSMEM
        {
            float s0 = breg, s1 = 0.f, s2 = 0.f, s3 = 0.f;
            #pragma unroll
            for (int k = 0; k < KC; k += 4) {
                s0 += lds_f32(redLd + (k + 0) * 544 * 4);
                s1 += lds_f32(redLd + (k + 1) * 544 * 4);
                s2 += lds_f32(redLd + (k + 2) * 544 * 4);
                s3 += lds_f32(redLd + (k + 3) * 544 * 4);
            }
            unsigned long long hd = dup2(tanh_fast((s0 + s1) + (s2 + s3)));
            unsigned dst = (cur ^ 1) * SBUF_B + pubIdx;
            sts_u64(Sb + dst, hd);
            sts_cluster_u64(peerSb + dst, hd);
        }
        // stage x(t+2) -> Xs[t&1]
        if (tid < ISZ * BCTA && t + 2 < TSTEPS) {
            int b = tid >> 6, i = tid & 63;
            sts_u64(Xb + (t & 1) * XBUF_B + (unsigned)(i * 4 + b) * 8, dup2(xv));
        }
        __syncthreads();
        if (tid == 0) { bar_arrive_local(barA); bar_arrive_remote_pre(peerBar); }

        // ---- x-part(t+1): overlaps cluster round-trip
        a0 = a1 = a2 = a3 = a4 = a5 = a6 = a7 = 0;
        if (t + 1 < TSTEPS) {
            unsigned xadr = Xb + ((t + 1) & 1) * XBUF_B + (unsigned)(kc * KX_W) * 32;
            #pragma unroll
            for (int ii = 0; ii < KX_W; ++ii) {
                unsigned long long hx, hy, hz, hw;
                lds_v2u64(hx, hy, xadr + ii * 32);
                lds_v2u64(hz, hw, xadr + ii * 32 + 16);
                FMA2(a0, wx0[ii], hx);  FMA2(a1, wx1[ii], hx);
                FMA2(a2, wx0[ii], hy);  FMA2(a3, wx1[ii], hy);
                FMA2(a4, wx0[ii], hz);  FMA2(a5, wx1[ii], hz);
                FMA2(a6, wx0[ii], hw);  FMA2(a7, wx1[ii], hw);
            }
        }
        bar_wait(barA, phase);
        phase ^= 1;
        cur ^= 1;
    }

    // ---- final FC (O=1), rank 0 only
    if (rank == 0) {
        const float* scur = smdyn + cur * (SBUF_B / 4);
        float* redf = smdyn + RED_OFF / 4;
        if (tid < HSZ) {
            float fw = fc_W[tid];
            float p0 = scur[tid * 8 + 0] * fw;
            float p1 = scur[tid * 8 + 2] * fw;
            float p2 = scur[tid * 8 + 4] * fw;
            float p3 = scur[tid * 8 + 6] * fw;
            #pragma unroll
            for (int off = 16; off; off >>= 1) {
                p0 += __shfl_down_sync(0xffffffffu, p0, off);
                p1 += __shfl_down_sync(0xffffffffu, p1, off);
                p2 += __shfl_down_sync(0xffffffffu, p2, off);
                p3 += __shfl_down_sync(0xffffffffu, p3, off);
            }
            if (lane == 0) {
                redf[kc * 4 + 0] = p0; redf[kc * 4 + 1] = p1;
                redf[kc * 4 + 2] = p2; redf[kc * 4 + 3] = p3;
            }
        }
        __syncthreads();
        if (tid < 4) {
            float v = fc_b[0];
            #pragma unroll
            for (int k = 0; k < 8; ++k) v += redf[k * 4 + tid];
            out[b0 + tid] = v;
        }
    }
}

extern "C" void kernel_launch(void* const* d_in, const int* in_sizes, int n_in,
                              void* d_out, int out_size) {
    const float* x    = (const float*)d_in[0];
    const float* W_ih = (const float*)d_in[1];
    const float* W_hh = (const float*)d_in[2];
    const float* b_ih = (const float*)d_in[3];
    const float* b_hh = (const float*)d_in[4];
    const float* fc_W = (const float*)d_in[5];
    const float* fc_b = (const float*)d_in[6];
    float* out = (float*)d_out;

    cudaFuncSetAttribute(rnn_kernel, cudaFuncAttributeMaxDynamicSharedMemorySize, SMEM_BYTES);

    prep_kernel<<<128, 256>>>(W_ih, W_hh, b_ih, b_hh);
    rnn_kernel<<<NBLOCKS, NTH, SMEM_BYTES>>>(x, fc_W, fc_b, out);
}

// round 7
// speedup vs baseline: 1.4552x; 1.0927x over previous
#include <cuda_runtime.h>
#include <cooperative_groups.h>
namespace cg = cooperative_groups;

#define TSTEPS 512
#define BATCH  256
#define ISZ    64
#define HSZ    256
#define BCTA   4
#define JHALF  128
#define NTH    512
#define KC     16                 // warps
#define KH_H   8                  // h-rows per warp per half
#define KX_W   (ISZ / KC)         // 4 x-rows per warp
#define NBLOCKS ((BATCH / BCTA) * 2)   // 128

__device__ float g_WT[(HSZ + ISZ) * HSZ];   // rows 0..255 = W_hh^T, 256..319 = W_ih^T
__device__ float g_bias[HSZ];

__global__ void prep_kernel(const float* __restrict__ W_ih,
                            const float* __restrict__ W_hh,
                            const float* __restrict__ b_ih,
                            const float* __restrict__ b_hh) {
    int idx = blockIdx.x * blockDim.x + threadIdx.x;
    int stride = gridDim.x * blockDim.x;
    for (int p = idx; p < (HSZ + ISZ) * HSZ; p += stride) {
        int i = p >> 8, j = p & 255;
        g_WT[p] = (i < HSZ) ? W_hh[j * HSZ + i] : W_ih[j * ISZ + (i - HSZ)];
    }
    if (idx < HSZ) g_bias[idx] = b_ih[idx] + b_hh[idx];
}

// SMEM byte offsets
#define S_OFF    0          // h state, dup'd: 2 bufs x 256 rows x 4 u64  = 16384 B
#define X_OFF    16384      // x stage, dup'd: 2 bufs x 64 rows x 4 u64   =  4096 B
#define RED_OFF  20480      // partials: padded, 16*272 u64               = 34816 B
#define SMEM_BYTES 55296
#define SBUF_B   8192
#define XBUF_B   2048
#define REDK     272        // u64 stride per k-chunk (=544 floats)
#define REDB     68         // u64 stride per batch   (=136 floats)

#define FMA2(d, a, b) asm volatile("fma.rn.f32x2 %0, %1, %2, %0;" : "+l"(d) : "l"(a), "l"(b))

static __device__ __forceinline__ unsigned s2u(const void* p) {
    return (unsigned)__cvta_generic_to_shared(p);
}
static __device__ __forceinline__ unsigned long long dup2(float v) {
    unsigned long long d;
    asm("mov.b64 %0, {%1, %1};" : "=l"(d) : "f"(v));
    return d;
}
static __device__ __forceinline__ float tanh_fast(float v) {
    float e, r;
    asm("ex2.approx.f32 %0, %1;" : "=f"(e) : "f"(v * 2.885390082f));
    asm("rcp.approx.f32 %0, %1;" : "=f"(r) : "f"(e + 1.0f));
    return 1.0f - 2.0f * r;
}
static __device__ __forceinline__ void lds_v2u64(unsigned long long& a, unsigned long long& b, unsigned ad) {
    asm volatile("ld.shared.v2.u64 {%0,%1}, [%2];" : "=l"(a), "=l"(b) : "r"(ad));
}
static __device__ __forceinline__ void sts_u64(unsigned ad, unsigned long long v) {
    asm volatile("st.shared.u64 [%0], %1;" :: "r"(ad), "l"(v) : "memory");
}
static __device__ __forceinline__ void sts_cluster_u64(unsigned ad, unsigned long long v) {
    asm volatile("st.shared::cluster.u64 [%0], %1;" :: "r"(ad), "l"(v) : "memory");
}
static __device__ __forceinline__ float lds_f32(unsigned ad) {
    float v;
    asm volatile("ld.shared.f32 %0, [%1];" : "=f"(v) : "r"(ad));
    return v;
}
static __device__ __forceinline__ void bar_arrive_local(unsigned bar) {
    asm volatile("mbarrier.arrive.release.cta.shared::cta.b64 _, [%0];" :: "r"(bar) : "memory");
}
static __device__ __forceinline__ void bar_arrive_remote_pre(unsigned bar_remote) {
    asm volatile("mbarrier.arrive.release.cluster.shared::cluster.b64 _, [%0];" :: "r"(bar_remote) : "memory");
}
static __device__ __forceinline__ void bar_wait(unsigned bar, unsigned phase) {
    asm volatile("{\n\t.reg .pred P;\n\t"
                 "WLOOP_%=:\n\t"
                 "mbarrier.try_wait.parity.acquire.cluster.shared::cta.b64 P, [%0], %1, 0x989680;\n\t"
                 "@P bra.uni WDONE_%=;\n\t"
                 "bra.uni WLOOP_%=;\n\t"
                 "WDONE_%=:\n\t}"
                 :: "r"(bar), "r"(phase) : "memory");
}
static __device__ __forceinline__ unsigned mapa_u32(unsigned ad, int peer) {
    unsigned r;
    asm("mapa.shared::cluster.u32 %0, %1, %2;" : "=r"(r) : "r"(ad), "r"(peer));
    return r;
}

__global__ void __cluster_dims__(2, 1, 1) __launch_bounds__(NTH, 1)
rnn_kernel(const float* __restrict__ x,
           const float* __restrict__ fc_W,
           const float* __restrict__ fc_b,
           float* __restrict__ out) {
    extern __shared__ float smdyn[];
    __shared__ __align__(8) unsigned long long barrier_s;

    cg::cluster_group cl = cg::this_cluster();
    const int rank = (int)cl.block_rank();
    const int tid  = threadIdx.x;
    const int lane = tid & 31;
    const int kc   = tid >> 5;
    const int b0   = (blockIdx.x >> 1) * BCTA;
    const int peer = rank ^ 1;

    const unsigned smbase = s2u(smdyn);
    const unsigned Sb   = smbase + S_OFF;
    const unsigned Xb   = smbase + X_OFF;
    const unsigned REDb = smbase + RED_OFF;
    const unsigned barA = s2u(&barrier_s);

    // ---- weights -> regs: 8 local-origin rows, 8 peer-origin rows, 4 x-rows
    unsigned long long wL0[KH_H], wL1[KH_H], wP0[KH_H], wP1[KH_H], wx0[KX_W], wx1[KX_W];
    {
        const int cb = rank * JHALF + 2 * lane;
        #pragma unroll
        for (int ii = 0; ii < KH_H; ++ii) {
            int iL = rank * JHALF + kc * KH_H + ii;
            int iP = peer * JHALF + kc * KH_H + ii;
            wL0[ii] = *reinterpret_cast<const unsigned long long*>(&g_WT[iL * HSZ + cb]);
            wL1[ii] = *reinterpret_cast<const unsigned long long*>(&g_WT[iL * HSZ + cb + 64]);
            wP0[ii] = *reinterpret_cast<const unsigned long long*>(&g_WT[iP * HSZ + cb]);
            wP1[ii] = *reinterpret_cast<const unsigned long long*>(&g_WT[iP * HSZ + cb + 64]);
        }
        #pragma unroll
        for (int ii = 0; ii < KX_W; ++ii) {
            int i = HSZ + kc * KX_W + ii;
            wx0[ii] = *reinterpret_cast<const unsigned long long*>(&g_WT[i * HSZ + cb]);
            wx1[ii] = *reinterpret_cast<const unsigned long long*>(&g_WT[i * HSZ + cb + 64]);
        }
    }
    const float breg = g_bias[rank * JHALF + (tid >> 2)];

    // ---- init: both h bufs = 0; stage x(0)->Xs[0], x(1)->Xs[1]
    for (int p = tid; p < 2 * HSZ * BCTA * 2; p += NTH) smdyn[p] = 0.f;
    const float* xb = x + (size_t)b0 * TSTEPS * ISZ;
    if (tid < ISZ * BCTA) {
        int b = tid >> 6, i = tid & 63;
        sts_u64(Xb + (unsigned)(i * 4 + b) * 8,          dup2(xb[(size_t)b * TSTEPS * ISZ + i]));
        sts_u64(Xb + XBUF_B + (unsigned)(i * 4 + b) * 8, dup2(xb[(size_t)b * TSTEPS * ISZ + ISZ + i]));
    }
    if (tid == 0)
        asm volatile("mbarrier.init.shared.b64 [%0], 2;" :: "r"(barA) : "memory");
    __syncthreads();
    asm volatile("barrier.cluster.arrive.aligned;" ::: "memory");
    asm volatile("barrier.cluster.wait.aligned;" ::: "memory");

    const unsigned peerSb  = mapa_u32(Sb, peer);
    const unsigned peerBar = mapa_u32(barA, peer);

    // bootstrap arrivals so first bar_wait passes
    if (tid == 0) { bar_arrive_local(barA); bar_arrive_remote_pre(peerBar); }

    // ---- acc = x-part(0)
    unsigned long long a0 = 0, a1 = 0, a2 = 0, a3 = 0, a4 = 0, a5 = 0, a6 = 0, a7 = 0;
    {
        unsigned xadr = Xb + (unsigned)(kc * KX_W) * 32;
        #pragma unroll
        for (int ii = 0; ii < KX_W; ++ii) {
            unsigned long long hx, hy, hz, hw;
            lds_v2u64(hx, hy, xadr + ii * 32);
            lds_v2u64(hz, hw, xadr + ii * 32 + 16);
            FMA2(a0, wx0[ii], hx);  FMA2(a1, wx1[ii], hx);
            FMA2(a2, wx0[ii], hy);  FMA2(a3, wx1[ii], hy);
            FMA2(a4, wx0[ii], hz);  FMA2(a5, wx1[ii], hz);
            FMA2(a6, wx0[ii], hw);  FMA2(a7, wx1[ii], hw);
        }
    }

    int cur = 0;
    unsigned phase = 0;
    const int rj = tid >> 2, rb = tid & 3;
    const unsigned pubIdx = (unsigned)((rank * JHALF + rj) * 4 + rb) * 8;
    const unsigned redLd  = REDb + (unsigned)(rb * 136 + rj) * 4;
    const unsigned redSt  = REDb + (unsigned)(kc * REDK + lane) * 8;
    const unsigned adrL   = Sb + (unsigned)((rank * JHALF + kc * KH_H) * 4) * 8;
    const unsigned adrP   = Sb + (unsigned)((peer * JHALF + kc * KH_H) * 4) * 8;

    for (int t = 0; t < TSTEPS; ++t) {
        // prefetch x(t+2)
        float xv = 0.f;
        if (tid < ISZ * BCTA && t + 2 < TSTEPS)
            xv = xb[(size_t)(tid >> 6) * TSTEPS * ISZ + (size_t)(t + 2) * ISZ + (tid & 63)];

        // ---- local-origin half of h-GEMM (these rows were produced by THIS CTA)
        {
            unsigned sadr = adrL + cur * SBUF_B;
            #pragma unroll
            for (int ii = 0; ii < KH_H; ++ii) {
                unsigned long long hx, hy, hz, hw;
                lds_v2u64(hx, hy, sadr + ii * 32);
                lds_v2u64(hz, hw, sadr + ii * 32 + 16);
                FMA2(a0, wL0[ii], hx);  FMA2(a1, wL1[ii], hx);
                FMA2(a2, wL0[ii], hy);  FMA2(a3, wL1[ii], hy);
                FMA2(a4, wL0[ii], hz);  FMA2(a5, wL1[ii], hz);
                FMA2(a6, wL0[ii], hw);  FMA2(a7, wL1[ii], hw);
            }
        }

        // ---- wait for peer's half (its DSMEM push had the x-GEMM + local half to land)
        bar_wait(barA, phase);
        phase ^= 1;

        // ---- peer-origin half of h-GEMM
        {
            unsigned sadr = adrP + cur * SBUF_B;
            #pragma unroll
            for (int ii = 0; ii < KH_H; ++ii) {
                unsigned long long hx, hy, hz, hw;
                lds_v2u64(hx, hy, sadr + ii * 32);
                lds_v2u64(hz, hw, sadr + ii * 32 + 16);
                FMA2(a0, wP0[ii], hx);  FMA2(a1, wP1[ii], hx);
                FMA2(a2, wP0[ii], hy);  FMA2(a3, wP1[ii], hy);
                FMA2(a4, wP0[ii], hz);  FMA2(a5, wP1[ii], hz);
                FMA2(a6, wP0[ii], hw);  FMA2(a7, wP1[ii], hw);
            }
        }

        // ---- partials
        sts_u64(redSt,                 a0);  sts_u64(redSt + 32 * 8,              a1);
        sts_u64(redSt + REDB * 8,      a2);  sts_u64(redSt + (REDB + 32) * 8,     a3);
        sts_u64(redSt + 2 * REDB * 8,  a4);  sts_u64(redSt + (2 * REDB + 32) * 8, a5);
        sts_u64(redSt + 3 * REDB * 8,  a6);  sts_u64(redSt + (3 * REDB + 32) * 8, a7);
        __syncthreads();

        // ---- reduce + tanh + publish local & DSMEM
        {
            float s0 = breg, s1 = 0.f, s2 = 0.f, s3 = 0.f;
            #pragma unroll
            for (int k = 0; k < KC; k += 4) {
                s0 += lds_f32(redLd + (k + 0) * 544 * 4);
                s1 += lds_f32(redLd + (k + 1) * 544 * 4);
                s2 += lds_f32(redLd + (k + 2) * 544 * 4);
                s3 += lds_f32(redLd + (k + 3) * 544 * 4);
            }
            unsigned long long hd = dup2(tanh_fast((s0 + s1) + (s2 + s3)));
            unsigned dst = (cur ^ 1) * SBUF_B + pubIdx;
            sts_u64(Sb + dst, hd);
            sts_cluster_u64(peerSb + dst, hd);
        }
        // stage x(t+2)
        if (tid < ISZ * BCTA && t + 2 < TSTEPS) {
            int b = tid >> 6, i = tid & 63;
            sts_u64(Xb + (t & 1) * XBUF_B + (unsigned)(i * 4 + b) * 8, dup2(xv));
        }
        __syncthreads();
        if (tid == 0) { bar_arrive_local(barA); bar_arrive_remote_pre(peerBar); }

        // ---- x-part(t+1): overlaps peer round trip
        a0 = a1 = a2 = a3 = a4 = a5 = a6 = a7 = 0;
        if (t + 1 < TSTEPS) {
            unsigned xadr = Xb + ((t + 1) & 1) * XBUF_B + (unsigned)(kc * KX_W) * 32;
            #pragma unroll
            for (int ii = 0; ii < KX_W; ++ii) {
                unsigned long long hx, hy, hz, hw;
                lds_v2u64(hx, hy, xadr + ii * 32);
                lds_v2u64(hz, hw, xadr + ii * 32 + 16);
                FMA2(a0, wx0[ii], hx);  FMA2(a1, wx1[ii], hx);
                FMA2(a2, wx0[ii], hy);  FMA2(a3, wx1[ii], hy);
                FMA2(a4, wx0[ii], hz);  FMA2(a5, wx1[ii], hz);
                FMA2(a6, wx0[ii], hw);  FMA2(a7, wx1[ii], hw);
            }
        }
        cur ^= 1;
    }

    // peer's final DSMEM push must land before rank0 reads full state
    asm volatile("barrier.cluster.arrive.aligned;" ::: "memory");
    asm volatile("barrier.cluster.wait.aligned;" ::: "memory");

    // ---- final FC (O=1), rank 0 only
    if (rank == 0) {
        const float* scur = smdyn + cur * (SBUF_B / 4);
        float* redf = smdyn + RED_OFF / 4;
        if (tid < HSZ) {
            float fw = fc_W[tid];
            float p0 = scur[tid * 8 + 0] * fw;
            float p1 = scur[tid * 8 + 2] * fw;
            float p2 = scur[tid * 8 + 4] * fw;
            float p3 = scur[tid * 8 + 6] * fw;
            #pragma unroll
            for (int off = 16; off; off >>= 1) {
                p0 += __shfl_down_sync(0xffffffffu, p0, off);
                p1 += __shfl_down_sync(0xffffffffu, p1, off);
                p2 += __shfl_down_sync(0xffffffffu, p2, off);
                p3 += __shfl_down_sync(0xffffffffu, p3, off);
            }
            if (lane == 0) {
                redf[kc * 4 + 0] = p0; redf[kc * 4 + 1] = p1;
                redf[kc * 4 + 2] = p2; redf[kc * 4 + 3] = p3;
            }
        }
        __syncthreads();
        if (tid < 4) {
            float v = fc_b[0];
            #pragma unroll
            for (int k = 0; k < 8; ++k) v += redf[k * 4 + tid];
            out[b0 + tid] = v;
        }
    }
}

extern "C" void kernel_launch(void* const* d_in, const int* in_sizes, int n_in,
                              void* d_out, int out_size) {
    const float* x    = (const float*)d_in[0];
    const float* W_ih = (const float*)d_in[1];
    const float* W_hh = (const float*)d_in[2];
    const float* b_ih = (const float*)d_in[3];
    const float* b_hh = (const float*)d_in[4];
    const float* fc_W = (const float*)d_in[5];
    const float* fc_b = (const float*)d_in[6];
    float* out = (float*)d_out;

    cudaFuncSetAttribute(rnn_kernel, cudaFuncAttributeMaxDynamicSharedMemorySize, SMEM_BYTES);

    prep_kernel<<<128, 256>>>(W_ih, W_hh, b_ih, b_hh);
    rnn_kernel<<<NBLOCKS, NTH, SMEM_BYTES>>>(x, fc_W, fc_b, out);
}